// round 14
// baseline (speedup 1.0000x reference)
#include <cuda_runtime.h>
#include <cstddef>

// Problem constants (fixed by the dataset)
#define BS    32
#define NFEAT 64
#define NN    512      // N (graph nodes / m dim)
#define JJ    4
#define NOUT  128
#define CDIM  (JJ * NFEAT)   // 256 channels
#define ROWF4 512            // one W n-row = 2048 floats = 512 float4
#define EQ    8              // epilogue m-groups per batch
#define MTL   (NN / EQ)      // 64 m per group

// Reduced, transposed S[b][j][m]. 32*4*512 floats = 256 KB (L2-resident).
__device__ float g_S[BS * JJ * NN];
// Per-batch y accumulator (atomicAdd target), self-zeroed each replay. 16 KB.
__device__ float g_Yacc[BS * NOUT];
// Per-batch completion counters; atomicInc wrap=EQ-1 self-resets every replay.
__device__ unsigned int g_cnt[BS];

// ---------------------------------------------------------------------------
// Kernel 1 (134 MB HBM stream), column-split, writes S directly — proven
// ~19.2us shape from round 13, unchanged.
// ---------------------------------------------------------------------------
__global__ __launch_bounds__(512) void reduce_w_kernel(const float4* __restrict__ W4) {
    __shared__ float4 red[512];   // 8 KB

    const int s = blockIdx.x;     // 0..31 column split
    const int b = blockIdx.y;
    const int t = threadIdx.x;    // 0..511
    const int col4 = t & 15;      // float4 column within slice = local m
    const int ng   = t >> 4;      // n-subgroup 0..31

    const float4* __restrict__ base =
        W4 + (size_t)b * NN * ROWF4 + s * 16 + col4;

    float4 acc = make_float4(0.f, 0.f, 0.f, 0.f);
#pragma unroll
    for (int i = 0; i < 16; ++i) {
        // streaming, evict-first: W is read exactly once and exceeds L2
        const float4 v = __ldcs(&base[(size_t)(i * 32 + ng) * ROWF4]);
        acc.x += v.x; acc.y += v.y; acc.z += v.z; acc.w += v.w;
    }
    red[t] = acc;                 // layout: red[ng*16 + col4]
    __syncthreads();

#pragma unroll
    for (int st = 256; st >= 16; st >>= 1) {
        if (t < st) {
            const float4 o = red[t + st];
            red[t].x += o.x; red[t].y += o.y; red[t].z += o.z; red[t].w += o.w;
        }
        __syncthreads();
    }

    if (t < 16) {
        const int m = s * 16 + t;
        const float4 r = red[t];
        g_S[((size_t)b * JJ + 0) * NN + m] = r.x;
        g_S[((size_t)b * JJ + 1) * NN + m] = r.y;
        g_S[((size_t)b * JJ + 2) * NN + m] = r.z;
        g_S[((size_t)b * JJ + 3) * NN + m] = r.w;
    }
}

// ---------------------------------------------------------------------------
// Kernel 2 (epilogue). grid (BS, EQ) x 256 thr. Block (b,q) owns m-range
// [q*64, q*64+64). ALL heavy work happens pre-gate on 256 live blocks:
//  A: Ssh[j][mloc] = S[b][j][q*64+mloc]   (L2-hot),  Xs = X tile (DRAM, f4)
//  C: Gq[c] = sum_mloc Ssh * Xs          (shared only, stays in shared)
//  Y: partial y = fc_w . Gq  -> atomicAdd into g_Yacc[b][:]
//  gate -> tiny tail: out = Yacc + 512*fc_b; reset Yacc for next replay.
// ---------------------------------------------------------------------------
__global__ __launch_bounds__(256) void epilogue_kernel(
    const float* __restrict__ X,
    const float* __restrict__ fc_w,
    const float* __restrict__ fc_b,
    float* __restrict__ out)
{
    __shared__ float Xs[NFEAT][MTL + 1]; // 16.25 KB, odd stride -> conflict-free
    __shared__ float Ssh[JJ][MTL];       // 1 KB
    __shared__ float Gq[CDIM];           // 1 KB  (this block's partial G)
    __shared__ float Yp[256];            // 1 KB  (per-thread y partials)
    __shared__ int isLast;

    const int b = blockIdx.x;
    const int q = blockIdx.y;       // 0..7
    const int t = threadIdx.x;      // 0..255

    // ---- A: S slice (L2-hot) + X tile (float4, coalesced) ----
    {
        const int j    = t >> 6;
        const int mloc = t & 63;
        Ssh[j][mloc] = g_S[((size_t)b * JJ + j) * NN + q * MTL + mloc];
    }
    const float4* __restrict__ Xb4 =
        reinterpret_cast<const float4*>(X + (size_t)b * NFEAT * NN);
#pragma unroll
    for (int i = 0; i < 4; ++i) {
        const int idx = t + i * 256;             // 0..1023 f4 slots
        const int f   = idx >> 4;                // 16 f4 per f-row
        const int mq4 = idx & 15;
        const float4 v = Xb4[(size_t)f * (NN / 4) + q * (MTL / 4) + mq4];
        Xs[f][mq4 * 4 + 0] = v.x;
        Xs[f][mq4 * 4 + 1] = v.y;
        Xs[f][mq4 * 4 + 2] = v.z;
        Xs[f][mq4 * 4 + 3] = v.w;
    }
    __syncthreads();

    // ---- C: this block's partial G, kept in shared ----
    {
        const int j = t >> 6;      // uniform per warp -> Ssh broadcast
        const int f = t & 63;
        float g = 0.f;
#pragma unroll
        for (int mm = 0; mm < MTL; ++mm) g += Ssh[j][mm] * Xs[f][mm];
        Gq[t] = g;
    }
    __syncthreads();

    // ---- Y: partial y = fc_w . Gq, computed by ALL 256 threads pre-gate.
    // Thread t: o = t&127, half = t>>7 (uniform per warp -> Gq reads broadcast).
    {
        const int o    = t & 127;
        const int half = t >> 7;                 // 0/1
        const float4* __restrict__ wrow4 =
            reinterpret_cast<const float4*>(fc_w + (size_t)o * CDIM) + half * 32;
        const float4* __restrict__ Gq4 =
            reinterpret_cast<const float4*>(Gq) + half * 32;
        float a = 0.f;
#pragma unroll 8
        for (int i = 0; i < 32; ++i) {
            const float4 wv = wrow4[i];
            const float4 gv = Gq4[i];            // warp-uniform -> LDS broadcast
            a += wv.x * gv.x + wv.y * gv.y + wv.z * gv.z + wv.w * gv.w;
        }
        Yp[half * 128 + o] = a;
    }
    __syncthreads();
    if (t < NOUT) atomicAdd(&g_Yacc[(size_t)b * NOUT + t], Yp[t] + Yp[t + 128]);

    // ---- gate: last block of batch b finishes up ----
    __threadfence();
    if (t == 0) {
        unsigned old = atomicInc(&g_cnt[b], EQ - 1);  // wraps to 0: self-resets
        isLast = (old == EQ - 1);
    }
    __syncthreads();
    if (!isLast) return;

    // ---- tiny tail: copy + bias, then reset the accumulator for next replay
    if (t < NOUT) {
        const float v = __ldcg(&g_Yacc[(size_t)b * NOUT + t]);  // L2, skip L1
        out[(size_t)b * NOUT + t] = v + (float)NN * fc_b[t];
        g_Yacc[(size_t)b * NOUT + t] = 0.f;
    }
}

// ---------------------------------------------------------------------------
// Inputs (metadata order): X[32,64,512] f32, W[32,512,512,4] f32,
// fc_w[128,256] f32, fc_b[128] f32, N_batch (int), mask[32,512] f32 (unused).
// Output: y[32,128] f32.
// ---------------------------------------------------------------------------
extern "C" void kernel_launch(void* const* d_in, const int* in_sizes, int n_in,
                              void* d_out, int out_size)
{
    const float* X    = (const float*)d_in[0];
    const float* W    = (const float*)d_in[1];
    const float* fc_w = (const float*)d_in[2];
    const float* fc_b = (const float*)d_in[3];
    float*       out  = (float*)d_out;

    dim3 grid1(32, BS);   // (column-split, batch)
    reduce_w_kernel<<<grid1, 512>>>(reinterpret_cast<const float4*>(W));
    dim3 grid2(BS, EQ);
    epilogue_kernel<<<grid2, 256>>>(X, fc_w, fc_b, out);
}

// round 15
// speedup vs baseline: 1.0394x; 1.0394x over previous
#include <cuda_runtime.h>
#include <cstddef>

// Problem constants (fixed by the dataset)
#define BS    32
#define NFEAT 64
#define NN    512      // N (graph nodes / m dim)
#define JJ    4
#define NOUT  128
#define CDIM  (JJ * NFEAT)   // 256 channels
#define ROWF4 512            // one W n-row = 2048 floats = 512 float4
#define EQ    8              // epilogue m-groups per batch
#define MTL   (NN / EQ)      // 64 m per group

// Reduced, transposed S[b][j][m]. 32*4*512 floats = 256 KB (L2-resident).
__device__ float g_S[BS * JJ * NN];
// Per-batch y accumulator (atomicAdd target), self-zeroed each replay. 16 KB.
__device__ float g_Yacc[BS * NOUT];
// Per-batch completion counters; atomicInc wrap=EQ-1 self-resets every replay.
__device__ unsigned int g_cnt[BS];

// ---------------------------------------------------------------------------
// Kernel 1 (134 MB HBM stream), column-split, writes S directly — proven
// ~19.2us shape from round 13, unchanged.
// ---------------------------------------------------------------------------
__global__ __launch_bounds__(512) void reduce_w_kernel(const float4* __restrict__ W4) {
    __shared__ float4 red[512];   // 8 KB

    const int s = blockIdx.x;     // 0..31 column split
    const int b = blockIdx.y;
    const int t = threadIdx.x;    // 0..511
    const int col4 = t & 15;      // float4 column within slice = local m
    const int ng   = t >> 4;      // n-subgroup 0..31

    const float4* __restrict__ base =
        W4 + (size_t)b * NN * ROWF4 + s * 16 + col4;

    float4 acc = make_float4(0.f, 0.f, 0.f, 0.f);
#pragma unroll
    for (int i = 0; i < 16; ++i) {
        // streaming, evict-first: W is read exactly once and exceeds L2
        const float4 v = __ldcs(&base[(size_t)(i * 32 + ng) * ROWF4]);
        acc.x += v.x; acc.y += v.y; acc.z += v.z; acc.w += v.w;
    }
    red[t] = acc;                 // layout: red[ng*16 + col4]
    __syncthreads();

#pragma unroll
    for (int st = 256; st >= 16; st >>= 1) {
        if (t < st) {
            const float4 o = red[t + st];
            red[t].x += o.x; red[t].y += o.y; red[t].z += o.z; red[t].w += o.w;
        }
        __syncthreads();
    }

    if (t < 16) {
        const int m = s * 16 + t;
        const float4 r = red[t];
        g_S[((size_t)b * JJ + 0) * NN + m] = r.x;
        g_S[((size_t)b * JJ + 1) * NN + m] = r.y;
        g_S[((size_t)b * JJ + 2) * NN + m] = r.z;
        g_S[((size_t)b * JJ + 3) * NN + m] = r.w;
    }
}

// ---------------------------------------------------------------------------
// Kernel 2 (epilogue). grid (BS, EQ) x 256 thr. Block (b,q) owns m-range
// [q*64, q*64+64). ALL heavy work pre-gate on 256 live blocks:
//  A: Ssh[j][mloc] = S[b][j][q*64+mloc]  (L2-hot),  Xs = X tile (DRAM, f4)
//  C: Gq[c] = sum_mloc Ssh * Xs          (shared only)
//  Y: warp-per-o partial y = fc_w[o,:] . Gq (COALESCED fc_w, broadcast Gq)
//     -> lane0 atomicAdd into g_Yacc[b][o]
//  gate -> tiny tail: out = Yacc + 512*fc_b; reset Yacc for next replay.
// ---------------------------------------------------------------------------
__global__ __launch_bounds__(256) void epilogue_kernel(
    const float* __restrict__ X,
    const float* __restrict__ fc_w,
    const float* __restrict__ fc_b,
    float* __restrict__ out)
{
    __shared__ float Xs[NFEAT][MTL + 1]; // 16.25 KB, odd stride -> conflict-free
    __shared__ float Ssh[JJ][MTL];       // 1 KB
    __shared__ float Gq[CDIM];           // 1 KB  (this block's partial G)
    __shared__ int isLast;

    const int b = blockIdx.x;
    const int q = blockIdx.y;       // 0..7
    const int t = threadIdx.x;      // 0..255

    // ---- A: S slice (L2-hot) + X tile (float4, coalesced) ----
    {
        const int j    = t >> 6;
        const int mloc = t & 63;
        Ssh[j][mloc] = g_S[((size_t)b * JJ + j) * NN + q * MTL + mloc];
    }
    const float4* __restrict__ Xb4 =
        reinterpret_cast<const float4*>(X + (size_t)b * NFEAT * NN);
#pragma unroll
    for (int i = 0; i < 4; ++i) {
        const int idx = t + i * 256;             // 0..1023 f4 slots
        const int f   = idx >> 4;                // 16 f4 per f-row
        const int mq4 = idx & 15;
        const float4 v = Xb4[(size_t)f * (NN / 4) + q * (MTL / 4) + mq4];
        Xs[f][mq4 * 4 + 0] = v.x;
        Xs[f][mq4 * 4 + 1] = v.y;
        Xs[f][mq4 * 4 + 2] = v.z;
        Xs[f][mq4 * 4 + 3] = v.w;
    }
    __syncthreads();

    // ---- C: this block's partial G, kept in shared ----
    {
        const int j = t >> 6;      // uniform per warp -> Ssh broadcast
        const int f = t & 63;
        float g = 0.f;
#pragma unroll
        for (int mm = 0; mm < MTL; ++mm) g += Ssh[j][mm] * Xs[f][mm];
        Gq[t] = g;
    }
    __syncthreads();

    // ---- Y: warp-per-o, COALESCED fc_w rows, pre-gate on all 256 blocks ----
    {
        const int w    = t >> 5;    // warp 0..7
        const int lane = t & 31;
        const float4* __restrict__ Gq4 = reinterpret_cast<const float4*>(Gq);
#pragma unroll 4
        for (int oi = 0; oi < 16; ++oi) {
            const int o = w * 16 + oi;           // 0..127
            const float4* __restrict__ wrow4 =
                reinterpret_cast<const float4*>(fc_w + (size_t)o * CDIM);
            float a = 0.f;
#pragma unroll
            for (int i = 0; i < 2; ++i) {
                const int q4 = i * 32 + lane;    // coalesced 128B transactions
                const float4 wv = wrow4[q4];
                const float4 gv = Gq4[q4];
                a += wv.x * gv.x + wv.y * gv.y + wv.z * gv.z + wv.w * gv.w;
            }
#pragma unroll
            for (int s = 16; s > 0; s >>= 1) a += __shfl_xor_sync(0xffffffffu, a, s);
            if (lane == 0) atomicAdd(&g_Yacc[(size_t)b * NOUT + o], a);
        }
    }

    // ---- gate: last block of batch b finishes up ----
    __threadfence();
    if (t == 0) {
        unsigned old = atomicInc(&g_cnt[b], EQ - 1);  // wraps to 0: self-resets
        isLast = (old == EQ - 1);
    }
    __syncthreads();
    if (!isLast) return;

    // ---- tiny tail: copy + bias, then reset the accumulator for next replay
    if (t < NOUT) {
        const float v = __ldcg(&g_Yacc[(size_t)b * NOUT + t]);  // L2, skip L1
        out[(size_t)b * NOUT + t] = v + (float)NN * fc_b[t];
        g_Yacc[(size_t)b * NOUT + t] = 0.f;
    }
}

// ---------------------------------------------------------------------------
// Inputs (metadata order): X[32,64,512] f32, W[32,512,512,4] f32,
// fc_w[128,256] f32, fc_b[128] f32, N_batch (int), mask[32,512] f32 (unused).
// Output: y[32,128] f32.
// ---------------------------------------------------------------------------
extern "C" void kernel_launch(void* const* d_in, const int* in_sizes, int n_in,
                              void* d_out, int out_size)
{
    const float* X    = (const float*)d_in[0];
    const float* W    = (const float*)d_in[1];
    const float* fc_w = (const float*)d_in[2];
    const float* fc_b = (const float*)d_in[3];
    float*       out  = (float*)d_out;

    dim3 grid1(32, BS);   // (column-split, batch)
    reduce_w_kernel<<<grid1, 512>>>(reinterpret_cast<const float4*>(W));
    dim3 grid2(BS, EQ);
    epilogue_kernel<<<grid2, 256>>>(X, fc_w, fc_b, out);
}

// round 16
// speedup vs baseline: 1.2646x; 1.2167x over previous
#include <cuda_runtime.h>
#include <cstddef>

// Problem constants (fixed by the dataset)
#define BS    32
#define NFEAT 64
#define NN    512      // N (graph nodes / m dim)
#define JJ    4
#define NOUT  128
#define CDIM  (JJ * NFEAT)   // 256 channels
#define ROWF4 512            // one W n-row = 2048 floats = 512 float4

// Reduced, transposed S[b][j][m]. 32*4*512 floats = 256 KB (L2-resident).
__device__ float g_S[BS * JJ * NN];
// G[b][c], c = j*64+f. 32 KB (L2-resident).
__device__ float g_G[BS * CDIM];

// ---------------------------------------------------------------------------
// Kernel 1 (134 MB HBM stream), column-split, writes S directly.
// Proven ~19.2us shape (round 13), unchanged.
// ---------------------------------------------------------------------------
__global__ __launch_bounds__(512) void reduce_w_kernel(const float4* __restrict__ W4) {
    __shared__ float4 red[512];   // 8 KB

    const int s = blockIdx.x;     // 0..31 column split
    const int b = blockIdx.y;
    const int t = threadIdx.x;    // 0..511
    const int col4 = t & 15;      // float4 column within slice = local m
    const int ng   = t >> 4;      // n-subgroup 0..31

    const float4* __restrict__ base =
        W4 + (size_t)b * NN * ROWF4 + s * 16 + col4;

    float4 acc = make_float4(0.f, 0.f, 0.f, 0.f);
#pragma unroll
    for (int i = 0; i < 16; ++i) {
        // streaming, evict-first: W is read exactly once and exceeds L2
        const float4 v = __ldcs(&base[(size_t)(i * 32 + ng) * ROWF4]);
        acc.x += v.x; acc.y += v.y; acc.z += v.z; acc.w += v.w;
    }
    red[t] = acc;                 // layout: red[ng*16 + col4]
    __syncthreads();

#pragma unroll
    for (int st = 256; st >= 16; st >>= 1) {
        if (t < st) {
            const float4 o = red[t + st];
            red[t].x += o.x; red[t].y += o.y; red[t].z += o.z; red[t].w += o.w;
        }
        __syncthreads();
    }

    if (t < 16) {
        const int m = s * 16 + t;
        const float4 r = red[t];
        g_S[((size_t)b * JJ + 0) * NN + m] = r.x;
        g_S[((size_t)b * JJ + 1) * NN + m] = r.y;
        g_S[((size_t)b * JJ + 2) * NN + m] = r.z;
        g_S[((size_t)b * JJ + 3) * NN + m] = r.w;
    }
}

// ---------------------------------------------------------------------------
// Kernel 2: G[b][j*64+f] = sum_m S[b][j][m] * X[b][f][m]
// Flat: one warp per (b,c); grid (32,32) x 256 thr = 8192 warps. Both streams
// coalesced (m = lane + 32*i), shfl tree-reduce. No gates, no phases.
// ---------------------------------------------------------------------------
__global__ __launch_bounds__(256) void compute_g_kernel(const float* __restrict__ X) {
    const int b    = blockIdx.x;
    const int c    = blockIdx.y * 8 + (threadIdx.x >> 5);  // 0..255
    const int lane = threadIdx.x & 31;
    const int j    = c >> 6;
    const int f    = c & 63;

    const float* __restrict__ Sr = g_S + ((size_t)b * JJ + j) * NN;
    const float* __restrict__ Xr = X   + ((size_t)b * NFEAT + f) * NN;

    float a = 0.f;
#pragma unroll
    for (int i = 0; i < 16; ++i) {
        const int m = i * 32 + lane;
        a += Sr[m] * Xr[m];
    }
#pragma unroll
    for (int s = 16; s > 0; s >>= 1) a += __shfl_xor_sync(0xffffffffu, a, s);

    if (lane == 0) g_G[(size_t)b * CDIM + c] = a;
}

// ---------------------------------------------------------------------------
// Kernel 3: y[b][o] = fc_w[o,:] . G[b,:] + 512*fc_b[o]
// Flat: one warp per (b,o); grid (32,16) x 256 thr = 4096 warps. Lane-strided
// float4 loads (coalesced), shfl tree-reduce.
// ---------------------------------------------------------------------------
__global__ __launch_bounds__(256) void compute_y_kernel(
    const float* __restrict__ fc_w,
    const float* __restrict__ fc_b,
    float* __restrict__ out)
{
    const int b    = blockIdx.x;
    const int o    = blockIdx.y * 8 + (threadIdx.x >> 5);  // 0..127
    const int lane = threadIdx.x & 31;

    const float4* __restrict__ w4 = reinterpret_cast<const float4*>(fc_w + (size_t)o * CDIM);
    const float4* __restrict__ g4 = reinterpret_cast<const float4*>(g_G + (size_t)b * CDIM);

    float a = 0.f;
#pragma unroll
    for (int i = 0; i < 2; ++i) {
        const int q = i * 32 + lane;       // 0..63 float4 slots, coalesced
        const float4 w = w4[q];
        const float4 g = g4[q];
        a += w.x * g.x + w.y * g.y + w.z * g.z + w.w * g.w;
    }
#pragma unroll
    for (int s = 16; s > 0; s >>= 1) a += __shfl_xor_sync(0xffffffffu, a, s);

    if (lane == 0) out[(size_t)b * NOUT + o] = a + (float)NN * fc_b[o];
}

// ---------------------------------------------------------------------------
// Inputs (metadata order): X[32,64,512] f32, W[32,512,512,4] f32,
// fc_w[128,256] f32, fc_b[128] f32, N_batch (int), mask[32,512] f32 (unused).
// Output: y[32,128] f32.
// ---------------------------------------------------------------------------
extern "C" void kernel_launch(void* const* d_in, const int* in_sizes, int n_in,
                              void* d_out, int out_size)
{
    const float* X    = (const float*)d_in[0];
    const float* W    = (const float*)d_in[1];
    const float* fc_w = (const float*)d_in[2];
    const float* fc_b = (const float*)d_in[3];
    float*       out  = (float*)d_out;

    dim3 grid1(32, BS);   // (column-split, batch)
    reduce_w_kernel<<<grid1, 512>>>(reinterpret_cast<const float4*>(W));
    dim3 grid2(BS, 32);
    compute_g_kernel<<<grid2, 256>>>(X);
    dim3 grid3(BS, 16);
    compute_y_kernel<<<grid3, 256>>>(fc_w, fc_b, out);
}

// round 17
// speedup vs baseline: 1.3196x; 1.0435x over previous
#include <cuda_runtime.h>
#include <cstddef>

// Problem constants (fixed by the dataset)
#define BS    32
#define NFEAT 64
#define NN    512      // N (graph nodes / m dim)
#define JJ    4
#define NOUT  128
#define CDIM  (JJ * NFEAT)   // 256 channels
#define ROWF4 512            // one W n-row = 2048 floats = 512 float4

// Reduced, transposed S[b][j][m]. 32*4*512 floats = 256 KB (L2-resident).
__device__ float g_S[BS * JJ * NN];
// G[b][c], c = j*64+f. 32 KB (L2-resident).
__device__ float g_G[BS * CDIM];

// ---------------------------------------------------------------------------
// Kernel 1 (134 MB HBM stream), column-split v2, writes S directly.
// Block (s,b) owns float4 columns [s*32, s*32+32). Thread t: col4 = t&31,
// ng = t>>5 (16 n-subgroups). Every warp load = 32 consecutive float4 = 512B
// contiguous (full-warp coalescing, same granularity as the row streamer).
// Each thread sums 32 rows, fully unrolled -> MLP=32.
// Grid (16, 32) = 512 blocks x 512 thr; tree-reduce over the 16 subgroups.
// ---------------------------------------------------------------------------
__global__ __launch_bounds__(512) void reduce_w_kernel(const float4* __restrict__ W4) {
    __shared__ float4 red[512];   // 8 KB

    const int s = blockIdx.x;     // 0..15 column split
    const int b = blockIdx.y;
    const int t = threadIdx.x;    // 0..511
    const int col4 = t & 31;      // float4 column within slice = local m
    const int ng   = t >> 5;      // n-subgroup 0..15

    const float4* __restrict__ base =
        W4 + (size_t)b * NN * ROWF4 + s * 32 + col4;

    float4 acc = make_float4(0.f, 0.f, 0.f, 0.f);
#pragma unroll
    for (int i = 0; i < 32; ++i) {
        // streaming, evict-first: W is read exactly once and exceeds L2
        const float4 v = __ldcs(&base[(size_t)(i * 16 + ng) * ROWF4]);
        acc.x += v.x; acc.y += v.y; acc.z += v.z; acc.w += v.w;
    }
    red[t] = acc;                 // layout: red[ng*32 + col4]
    __syncthreads();

    // reduce over ng (strides are multiples of 32 -> col4 alignment preserved)
#pragma unroll
    for (int st = 256; st >= 32; st >>= 1) {
        if (t < st) {
            const float4 o = red[t + st];
            red[t].x += o.x; red[t].y += o.y; red[t].z += o.z; red[t].w += o.w;
        }
        __syncthreads();
    }

    if (t < 32) {
        const int m = s * 32 + t;
        const float4 r = red[t];
        g_S[((size_t)b * JJ + 0) * NN + m] = r.x;
        g_S[((size_t)b * JJ + 1) * NN + m] = r.y;
        g_S[((size_t)b * JJ + 2) * NN + m] = r.z;
        g_S[((size_t)b * JJ + 3) * NN + m] = r.w;
    }
}

// ---------------------------------------------------------------------------
// Kernel 2: G[b][j*64+f] = sum_m S[b][j][m] * X[b][f][m]
// Flat: one warp per (b,c); grid (32,32) x 256 thr. float4 on BOTH streams:
// lane covers f4-slots lane+32i (i<4) -> 128B coalesced, 4 loads per stream.
// ---------------------------------------------------------------------------
__global__ __launch_bounds__(256) void compute_g_kernel(const float* __restrict__ X) {
    const int b    = blockIdx.x;
    const int c    = blockIdx.y * 8 + (threadIdx.x >> 5);  // 0..255
    const int lane = threadIdx.x & 31;
    const int j    = c >> 6;
    const int f    = c & 63;

    const float4* __restrict__ S4 =
        reinterpret_cast<const float4*>(g_S + ((size_t)b * JJ + j) * NN);
    const float4* __restrict__ X4 =
        reinterpret_cast<const float4*>(X + ((size_t)b * NFEAT + f) * NN);

    float a = 0.f;
#pragma unroll
    for (int i = 0; i < 4; ++i) {
        const int q = i * 32 + lane;            // 0..127 f4 slots, coalesced
        const float4 sv = S4[q];
        const float4 xv = X4[q];
        a += sv.x * xv.x + sv.y * xv.y + sv.z * xv.z + sv.w * xv.w;
    }
#pragma unroll
    for (int s = 16; s > 0; s >>= 1) a += __shfl_xor_sync(0xffffffffu, a, s);

    if (lane == 0) g_G[(size_t)b * CDIM + c] = a;
}

// ---------------------------------------------------------------------------
// Kernel 3: y[b][o] = fc_w[o,:] . G[b,:] + 512*fc_b[o]
// Flat: one warp per (b,o); grid (32,16) x 256 thr. Lane-strided float4.
// ---------------------------------------------------------------------------
__global__ __launch_bounds__(256) void compute_y_kernel(
    const float* __restrict__ fc_w,
    const float* __restrict__ fc_b,
    float* __restrict__ out)
{
    const int b    = blockIdx.x;
    const int o    = blockIdx.y * 8 + (threadIdx.x >> 5);  // 0..127
    const int lane = threadIdx.x & 31;

    const float4* __restrict__ w4 = reinterpret_cast<const float4*>(fc_w + (size_t)o * CDIM);
    const float4* __restrict__ g4 = reinterpret_cast<const float4*>(g_G + (size_t)b * CDIM);

    float a = 0.f;
#pragma unroll
    for (int i = 0; i < 2; ++i) {
        const int q = i * 32 + lane;       // 0..63 float4 slots, coalesced
        const float4 w = w4[q];
        const float4 g = g4[q];
        a += w.x * g.x + w.y * g.y + w.z * g.z + w.w * g.w;
    }
#pragma unroll
    for (int s = 16; s > 0; s >>= 1) a += __shfl_xor_sync(0xffffffffu, a, s);

    if (lane == 0) out[(size_t)b * NOUT + o] = a + (float)NN * fc_b[o];
}

// ---------------------------------------------------------------------------
// Inputs (metadata order): X[32,64,512] f32, W[32,512,512,4] f32,
// fc_w[128,256] f32, fc_b[128] f32, N_batch (int), mask[32,512] f32 (unused).
// Output: y[32,128] f32.
// ---------------------------------------------------------------------------
extern "C" void kernel_launch(void* const* d_in, const int* in_sizes, int n_in,
                              void* d_out, int out_size)
{
    const float* X    = (const float*)d_in[0];
    const float* W    = (const float*)d_in[1];
    const float* fc_w = (const float*)d_in[2];
    const float* fc_b = (const float*)d_in[3];
    float*       out  = (float*)d_out;

    dim3 grid1(16, BS);   // (column-split, batch)
    reduce_w_kernel<<<grid1, 512>>>(reinterpret_cast<const float4*>(W));
    dim3 grid2(BS, 32);
    compute_g_kernel<<<grid2, 256>>>(X);
    dim3 grid3(BS, 16);
    compute_y_kernel<<<grid3, 256>>>(fc_w, fc_b, out);
}